// round 9
// baseline (speedup 1.0000x reference)
#include <cuda_runtime.h>
#include <stdint.h>

#define D 128
#define NODES 50000
#define EDGES 500000
#define MAXT 10.0f

#define TE 64
#define NTH 256
#define RS1 272          // 272 cols (perm groups 0..16); 272 mod 32 = 16
#define RS2 144          // 144 cols (groups 0..8);       144 mod 32 = 16
#define NG1 17           // 16-col groups, K<=272
#define NG2 9            // K<=144
#define NKS1 (2*NG1)     // 34 k-steps
#define NKS2 (2*NG2)     // 18 k-steps

// ---------------- device scratch ----------------
__device__ float g_agg[(size_t)NODES * D];
__device__ float g_ts[(size_t)NODES * 3];
__device__ float g_cnt[NODES];
__device__ float4 g_wf1[NKS1 * 8 * 32];   // We1+be1 fragments
__device__ float4 g_wf2[NKS2 * 8 * 32];   // We2+be2
__device__ float4 g_wf3[NKS2 * 8 * 32];   // Wc1+bc1
__device__ float4 g_wf4[NKS1 * 8 * 32];   // Wn1+bn1
__device__ float4 g_wf5[NKS2 * 8 * 32];   // Wn2+bn2

// ---------------- helpers ----------------
__device__ __forceinline__ float silu_f(float x) {
    return x * __fdividef(1.0f, 1.0f + __expf(-x));
}
__device__ __forceinline__ float sigmoid_f(float x) {
    return __fdividef(1.0f, 1.0f + __expf(-x));
}
__device__ __forceinline__ float clampt(float x) {
    return fminf(fmaxf(x, -MAXT), MAXT);
}
__device__ __forceinline__ uint32_t tfbits(float x) {
    uint32_t u; asm("cvt.rna.tf32.f32 %0, %1;" : "=r"(u) : "f"(x)); return u;
}
__device__ __forceinline__ float tf32r(float x) { return __uint_as_float(tfbits(x)); }

__device__ __forceinline__ void red2(float* p, float a, float b) {
    asm volatile("red.global.add.v2.f32 [%0], {%1, %2};"
                 :: "l"(p), "f"(a), "f"(b) : "memory");
}

__device__ __forceinline__ void mma8(float acc[4],
    uint32_t a0, uint32_t a1, uint32_t a2, uint32_t a3, uint32_t b0, uint32_t b1)
{
    asm volatile(
        "mma.sync.aligned.m16n8k8.row.col.f32.tf32.tf32.f32 "
        "{%0,%1,%2,%3}, {%4,%5,%6,%7}, {%8,%9}, {%0,%1,%2,%3};"
        : "+f"(acc[0]), "+f"(acc[1]), "+f"(acc[2]), "+f"(acc[3])
        : "r"(a0), "r"(a1), "r"(a2), "r"(a3), "r"(b0), "r"(b1));
}

// Mainloop: per 16-col group g, one LDS.128 per (mt, lo/hi) feeds 2 k-steps.
template<int NG>
__device__ __forceinline__ void run_layer_ns(
    const uint32_t* __restrict__ sact, int rs,
    const float4* __restrict__ wq,
    float acc[4][2][4], int r4, int c)
{
    const uint32_t* base = sact + r4 * rs + c * 4;
    #pragma unroll 2
    for (int g = 0; g < NG; g++) {
        float4 b0 = wq[(2 * g) * 256];
        float4 b1 = wq[(2 * g + 1) * 256];
        #pragma unroll
        for (int mt = 0; mt < 4; mt++) {
            uint4 lo = *(const uint4*)(base + (mt * 16) * rs + g * 16);
            uint4 hi = *(const uint4*)(base + (mt * 16 + 8) * rs + g * 16);
            mma8(acc[mt][0], lo.x, hi.x, lo.y, hi.y,
                 __float_as_uint(b0.x), __float_as_uint(b0.y));
            mma8(acc[mt][1], lo.x, hi.x, lo.y, hi.y,
                 __float_as_uint(b0.z), __float_as_uint(b0.w));
            mma8(acc[mt][0], lo.z, hi.z, lo.w, hi.w,
                 __float_as_uint(b1.x), __float_as_uint(b1.y));
            mma8(acc[mt][1], lo.z, hi.z, lo.w, hi.w,
                 __float_as_uint(b1.z), __float_as_uint(b1.w));
        }
    }
}

// ---------------- zero + weight prep ----------------
__global__ void zero_kernel() {
    int idx = blockIdx.x * blockDim.x + threadIdx.x;
    int stride = gridDim.x * blockDim.x;
    for (int i = idx; i < NODES * D; i += stride) g_agg[i] = 0.0f;
    for (int i = idx; i < NODES * 3; i += stride) g_ts[i] = 0.0f;
    for (int i = idx; i < NODES; i += stride) g_cnt[i] = 0.0f;
}

__device__ __forceinline__ float wb(const float* W, const float* b, int K, int k, int n) {
    if (k < K) return W[k * D + n];
    if (k == K) return b[n];
    return 0.0f;
}

__global__ void prep_kernel(
    const float* __restrict__ We1, const float* __restrict__ be1,
    const float* __restrict__ We2, const float* __restrict__ be2,
    const float* __restrict__ Wc1, const float* __restrict__ bc1,
    const float* __restrict__ Wn1, const float* __restrict__ bn1,
    const float* __restrict__ Wn2, const float* __restrict__ bn2)
{
    int t = blockIdx.x * blockDim.x + threadIdx.x;
    const int n1 = NKS1 * 8 * 32, n2 = NKS2 * 8 * 32;
    const float *W, *bi; int K; float4* dst; int idx;
    if (t < n1)                    { W = We1; bi = be1; K = 257; dst = g_wf1; idx = t; }
    else if (t < n1 + n2)          { W = We2; bi = be2; K = 128; dst = g_wf2; idx = t - n1; }
    else if (t < n1 + 2 * n2)      { W = Wc1; bi = bc1; K = 128; dst = g_wf3; idx = t - n1 - n2; }
    else if (t < 2 * n1 + 2 * n2)  { W = Wn1; bi = bn1; K = 256; dst = g_wf4; idx = t - n1 - 2 * n2; }
    else if (t < 2 * n1 + 3 * n2)  { W = Wn2; bi = bn2; K = 128; dst = g_wf5; idx = t - 2 * n1 - 2 * n2; }
    else return;
    int lane = idx & 31, p = (idx >> 5) & 7, ks = idx >> 8;
    int c = lane & 3, r = lane >> 2, k0 = ks * 8;
    float4 v;
    v.x = tf32r(wb(W, bi, K, k0 + c,     p * 16 + r));
    v.y = tf32r(wb(W, bi, K, k0 + 4 + c, p * 16 + r));
    v.z = tf32r(wb(W, bi, K, k0 + c,     p * 16 + 8 + r));
    v.w = tf32r(wb(W, bi, K, k0 + 4 + c, p * 16 + 8 + r));
    dst[idx] = v;
}

// ---------------- edge kernel ----------------
#define O_SA    0
#define O_SMID  (TE * RS1)                   // 17408
#define O_SCD   (O_SMID + TE * RS2)          // 26624
#define O_ATTP  (O_SCD + TE * 4)             // 26880  [8][64]
#define O_CWP   (O_ATTP + 8 * TE)            // 27392  [8][64]
#define O_SATT  (O_CWP + 8 * TE)             // 27904
#define O_SROW  (O_SATT + TE)                // 27968
#define O_SCOL  (O_SROW + TE)                // 28032
#define ESM_WORDS (O_SCOL + TE)              // 28096 words = 112384 B -> 2 CTA/SM
#define O_SEF   O_SA                         // reuse sA region with stride RS2

__global__ void __launch_bounds__(NTH) edge_kernel(
    const float* __restrict__ h, const int* __restrict__ ei,
    const float* __restrict__ coord,
    const float* __restrict__ Watt, const float* __restrict__ batt,
    const float* __restrict__ Wc2,
    float* __restrict__ edge_out)
{
    extern __shared__ uint32_t smu[];
    float* smf = (float*)smu;
    int*   sRow = (int*)(smu + O_SROW);
    int*   sCol = (int*)(smu + O_SCOL);

    const int tid  = threadIdx.x;
    const int lane = tid & 31;
    const int warp = tid >> 5;      // 0..7 = N-slice (16 cols)
    const int c    = lane & 3;
    const int r4   = lane >> 2;
    const long long e0 = (long long)blockIdx.x * TE;
    // permuted store base for a thread's output col n0=warp*16+nt*8+2c:
    const int pbase = warp * 16 + (c & 1) * 8 + (c >> 1);
    // permuted gather base for a float4 at k=4*lane:
    const int gbase = (lane >> 2) * 16 + ((lane >> 1) & 1) * 2 + (lane & 1);

    // ---- indices, coord_diff, radial/bias tail (group 16: cols 256..271) ----
    if (tid < TE) {
        int el = tid;
        long long e = e0 + el;
        int rr = 0, cc = 0; float dx = 0, dy = 0, dz = 0, rad = 0;
        if (e < EDGES) {
            rr = ei[e]; cc = ei[(long long)EDGES + e];
            dx = coord[rr * 3 + 0] - coord[cc * 3 + 0];
            dy = coord[rr * 3 + 1] - coord[cc * 3 + 1];
            dz = coord[rr * 3 + 2] - coord[cc * 3 + 2];
            rad = dx * dx + dy * dy + dz * dz;
        }
        sRow[el] = rr; sCol[el] = cc;
        smf[O_SCD + el * 4 + 0] = dx;
        smf[O_SCD + el * 4 + 1] = dy;
        smf[O_SCD + el * 4 + 2] = dz;
        float* tp = smf + O_SA + el * RS1 + 256;
        *(float4*)(tp + 0)  = make_float4(0, 0, 0, 0);
        *(float4*)(tp + 4)  = make_float4(0, 0, 0, 0);
        *(float4*)(tp + 8)  = make_float4(0, 0, 0, 0);
        *(float4*)(tp + 12) = make_float4(0, 0, 0, 0);
        tp[0] = tf32r(rad);   // perm(256) = 256
        tp[4] = 1.0f;         // perm(257) = 260 (bias flag)
    }
    __syncthreads();

    // ---- gather h[row], h[col] -> sA (tf32, permuted cols) ----
    for (int i = 0; i < 8; i++) {
        int el = warp * 8 + i;
        int rr = sRow[el], cc = sCol[el];
        float4 v = *(const float4*)(h + (long long)rr * D + lane * 4);
        float4 w = *(const float4*)(h + (long long)cc * D + lane * 4);
        float* row = smf + O_SA + el * RS1 + gbase;
        row[0]  = tf32r(v.x); row[4]  = tf32r(v.y);
        row[8]  = tf32r(v.z); row[12] = tf32r(v.w);
        row[128]     = tf32r(w.x); row[128 + 4]  = tf32r(w.y);
        row[128 + 8] = tf32r(w.z); row[128 + 12] = tf32r(w.w);
    }
    __syncthreads();

    float acc[4][2][4];
    #pragma unroll
    for (int m = 0; m < 4; m++)
        #pragma unroll
        for (int n = 0; n < 2; n++)
            { acc[m][n][0]=0; acc[m][n][1]=0; acc[m][n][2]=0; acc[m][n][3]=0; }

    // ================= Layer 1 =================
    run_layer_ns<NG1>(smu + O_SA, RS1, g_wf1 + 32 * warp + lane, acc, r4, c);

    #pragma unroll
    for (int mt = 0; mt < 4; mt++) {
        int rlo = mt * 16 + r4;
        #pragma unroll
        for (int nt = 0; nt < 2; nt++) {
            int p0 = pbase + nt * 2;
            smu[O_SMID + rlo * RS2 + p0]           = tfbits(silu_f(acc[mt][nt][0]));
            smu[O_SMID + rlo * RS2 + p0 + 4]       = tfbits(silu_f(acc[mt][nt][1]));
            smu[O_SMID + (rlo + 8) * RS2 + p0]     = tfbits(silu_f(acc[mt][nt][2]));
            smu[O_SMID + (rlo + 8) * RS2 + p0 + 4] = tfbits(silu_f(acc[mt][nt][3]));
            acc[mt][nt][0]=0; acc[mt][nt][1]=0; acc[mt][nt][2]=0; acc[mt][nt][3]=0;
        }
    }
    if (tid < TE) {
        float* tp = smf + O_SMID + tid * RS2 + 128;
        *(float4*)(tp + 0)  = make_float4(0, 0, 0, 0);
        *(float4*)(tp + 4)  = make_float4(0, 0, 0, 0);
        *(float4*)(tp + 8)  = make_float4(0, 0, 0, 0);
        *(float4*)(tp + 12) = make_float4(0, 0, 0, 0);
        tp[0] = 1.0f;        // perm(128) = 128 (bias flag)
    }
    __syncthreads();

    // ================= Layer 2 =================
    run_layer_ns<NG2>(smu + O_SMID, RS2, g_wf2 + 32 * warp + lane, acc, r4, c);

    // attention partials (keep silu'd values in acc)
    {
        float plo[4] = {0,0,0,0}, phi[4] = {0,0,0,0};
        #pragma unroll
        for (int mt = 0; mt < 4; mt++) {
            #pragma unroll
            for (int nt = 0; nt < 2; nt++) {
                int n0 = warp * 16 + nt * 8 + 2 * c;
                float2 wa = *(const float2*)(Watt + n0);
                acc[mt][nt][0] = silu_f(acc[mt][nt][0]);
                acc[mt][nt][1] = silu_f(acc[mt][nt][1]);
                acc[mt][nt][2] = silu_f(acc[mt][nt][2]);
                acc[mt][nt][3] = silu_f(acc[mt][nt][3]);
                plo[mt] += acc[mt][nt][0] * wa.x + acc[mt][nt][1] * wa.y;
                phi[mt] += acc[mt][nt][2] * wa.x + acc[mt][nt][3] * wa.y;
            }
        }
        #pragma unroll
        for (int mt = 0; mt < 4; mt++) {
            plo[mt] += __shfl_xor_sync(0xffffffffu, plo[mt], 1);
            plo[mt] += __shfl_xor_sync(0xffffffffu, plo[mt], 2);
            phi[mt] += __shfl_xor_sync(0xffffffffu, phi[mt], 1);
            phi[mt] += __shfl_xor_sync(0xffffffffu, phi[mt], 2);
        }
        if (c == 0) {
            #pragma unroll
            for (int mt = 0; mt < 4; mt++) {
                smf[O_ATTP + warp * 64 + mt * 16 + r4]     = plo[mt];
                smf[O_ATTP + warp * 64 + mt * 16 + 8 + r4] = phi[mt];
            }
        }
    }
    __syncthreads();
    if (tid < TE) {
        float s = 0.0f;
        #pragma unroll
        for (int w = 0; w < 8; w++) s += smf[O_ATTP + w * 64 + tid];
        smf[O_SATT + tid] = sigmoid_f(s + batt[0]);
    }
    __syncthreads();

    // apply attention: edge_out + agg red.v2 + sEf (tf32, permuted)
    #pragma unroll
    for (int mt = 0; mt < 4; mt++) {
        int elo = mt * 16 + r4, ehi = elo + 8;
        float attlo = smf[O_SATT + elo], atthi = smf[O_SATT + ehi];
        bool vlo = (e0 + elo) < EDGES, vhi = (e0 + ehi) < EDGES;
        long long glo = (long long)sRow[elo] * D;
        long long ghi = (long long)sRow[ehi] * D;
        float* out_lo = edge_out + (e0 + elo) * D;
        float* out_hi = edge_out + (e0 + ehi) * D;
        #pragma unroll
        for (int nt = 0; nt < 2; nt++) {
            int n0 = warp * 16 + nt * 8 + 2 * c;
            int p0 = pbase + nt * 2;
            float f0 = acc[mt][nt][0] * attlo, f1 = acc[mt][nt][1] * attlo;
            float f2 = acc[mt][nt][2] * atthi, f3 = acc[mt][nt][3] * atthi;
            if (vlo) {
                *(float2*)(out_lo + n0) = make_float2(f0, f1);
                red2(g_agg + glo + n0, f0, f1);
            }
            if (vhi) {
                *(float2*)(out_hi + n0) = make_float2(f2, f3);
                red2(g_agg + ghi + n0, f2, f3);
            }
            smu[O_SEF + elo * RS2 + p0]     = tfbits(f0);
            smu[O_SEF + elo * RS2 + p0 + 4] = tfbits(f1);
            smu[O_SEF + ehi * RS2 + p0]     = tfbits(f2);
            smu[O_SEF + ehi * RS2 + p0 + 4] = tfbits(f3);
            acc[mt][nt][0]=0; acc[mt][nt][1]=0; acc[mt][nt][2]=0; acc[mt][nt][3]=0;
        }
    }
    if (tid < TE) {
        float* tp = smf + O_SEF + tid * RS2 + 128;
        *(float4*)(tp + 0)  = make_float4(0, 0, 0, 0);
        *(float4*)(tp + 4)  = make_float4(0, 0, 0, 0);
        *(float4*)(tp + 8)  = make_float4(0, 0, 0, 0);
        *(float4*)(tp + 12) = make_float4(0, 0, 0, 0);
        tp[0] = 1.0f;
    }
    __syncthreads();

    // ================= Layer 3 (coord MLP) =================
    run_layer_ns<NG2>(smu + O_SEF, RS2, g_wf3 + 32 * warp + lane, acc, r4, c);
    {
        float qlo[4] = {0,0,0,0}, qhi[4] = {0,0,0,0};
        #pragma unroll
        for (int mt = 0; mt < 4; mt++) {
            #pragma unroll
            for (int nt = 0; nt < 2; nt++) {
                int n0 = warp * 16 + nt * 8 + 2 * c;
                float2 w2 = *(const float2*)(Wc2 + n0);
                qlo[mt] += silu_f(acc[mt][nt][0]) * w2.x + silu_f(acc[mt][nt][1]) * w2.y;
                qhi[mt] += silu_f(acc[mt][nt][2]) * w2.x + silu_f(acc[mt][nt][3]) * w2.y;
            }
        }
        #pragma unroll
        for (int mt = 0; mt < 4; mt++) {
            qlo[mt] += __shfl_xor_sync(0xffffffffu, qlo[mt], 1);
            qlo[mt] += __shfl_xor_sync(0xffffffffu, qlo[mt], 2);
            qhi[mt] += __shfl_xor_sync(0xffffffffu, qhi[mt], 1);
            qhi[mt] += __shfl_xor_sync(0xffffffffu, qhi[mt], 2);
        }
        if (c == 0) {
            #pragma unroll
            for (int mt = 0; mt < 4; mt++) {
                smf[O_CWP + warp * 64 + mt * 16 + r4]     = qlo[mt];
                smf[O_CWP + warp * 64 + mt * 16 + 8 + r4] = qhi[mt];
            }
        }
    }
    __syncthreads();
    if (tid < TE && (e0 + tid) < EDGES) {
        float cw = 0.0f;
        #pragma unroll
        for (int w = 0; w < 8; w++) cw += smf[O_CWP + w * 64 + tid];
        int n = sRow[tid];
        atomicAdd(g_ts + n * 3 + 0, clampt(smf[O_SCD + tid * 4 + 0] * cw));
        atomicAdd(g_ts + n * 3 + 1, clampt(smf[O_SCD + tid * 4 + 1] * cw));
        atomicAdd(g_ts + n * 3 + 2, clampt(smf[O_SCD + tid * 4 + 2] * cw));
        atomicAdd(g_cnt + n, 1.0f);
    }
}

// ---------------- node kernel ----------------
#define TN 64
#define O_XN    0
#define O_MIDN  (TN * RS1)                   // 17408
#define NSM_WORDS (O_MIDN + TN * RS2)        // 26624 words = 106496 B -> 2 CTA/SM

__global__ void __launch_bounds__(NTH) node_kernel(
    const float* __restrict__ h, const float* __restrict__ coord,
    float* __restrict__ h_out, float* __restrict__ coord_out)
{
    extern __shared__ uint32_t smu[];
    float* smf = (float*)smu;

    const int tid  = threadIdx.x;
    const int lane = tid & 31;
    const int warp = tid >> 5;
    const int c    = lane & 3;
    const int r4   = lane >> 2;
    const int n0b  = blockIdx.x * TN;
    const int pbase = warp * 16 + (c & 1) * 8 + (c >> 1);
    const int gbase = (lane >> 2) * 16 + ((lane >> 1) & 1) * 2 + (lane & 1);

    // gather [h | agg] -> sXN (tf32, permuted); tail group 16: bias at 256
    for (int i = 0; i < 8; i++) {
        int row = warp * 8 + i;
        int n = n0b + row;
        float4 v = make_float4(0, 0, 0, 0), w = make_float4(0, 0, 0, 0);
        if (n < NODES) {
            v = *(const float4*)(h + (long long)n * D + lane * 4);
            w = *(const float4*)(g_agg + (long long)n * D + lane * 4);
        }
        float* rp = smf + O_XN + row * RS1 + gbase;
        rp[0]  = tf32r(v.x); rp[4]  = tf32r(v.y);
        rp[8]  = tf32r(v.z); rp[12] = tf32r(v.w);
        rp[128]     = tf32r(w.x); rp[128 + 4]  = tf32r(w.y);
        rp[128 + 8] = tf32r(w.z); rp[128 + 12] = tf32r(w.w);
    }
    if (tid < TN) {
        float* tp = smf + O_XN + tid * RS1 + 256;
        *(float4*)(tp + 0)  = make_float4(0, 0, 0, 0);
        *(float4*)(tp + 4)  = make_float4(0, 0, 0, 0);
        *(float4*)(tp + 8)  = make_float4(0, 0, 0, 0);
        *(float4*)(tp + 12) = make_float4(0, 0, 0, 0);
        tp[0] = 1.0f;        // perm(256)=256 (bias flag, K=256)
    }
    __syncthreads();

    float acc[4][2][4];
    #pragma unroll
    for (int m = 0; m < 4; m++)
        #pragma unroll
        for (int n = 0; n < 2; n++)
            { acc[m][n][0]=0; acc[m][n][1]=0; acc[m][n][2]=0; acc[m][n][3]=0; }

    run_layer_ns<NG1>(smu + O_XN, RS1, g_wf4 + 32 * warp + lane, acc, r4, c);

    #pragma unroll
    for (int mt = 0; mt < 4; mt++) {
        int rlo = mt * 16 + r4;
        #pragma unroll
        for (int nt = 0; nt < 2; nt++) {
            int p0 = pbase + nt * 2;
            smu[O_MIDN + rlo * RS2 + p0]           = tfbits(silu_f(acc[mt][nt][0]));
            smu[O_MIDN + rlo * RS2 + p0 + 4]       = tfbits(silu_f(acc[mt][nt][1]));
            smu[O_MIDN + (rlo + 8) * RS2 + p0]     = tfbits(silu_f(acc[mt][nt][2]));
            smu[O_MIDN + (rlo + 8) * RS2 + p0 + 4] = tfbits(silu_f(acc[mt][nt][3]));
            acc[mt][nt][0]=0; acc[mt][nt][1]=0; acc[mt][nt][2]=0; acc[mt][nt][3]=0;
        }
    }
    if (tid < TN) {
        float* tp = smf + O_MIDN + tid * RS2 + 128;
        *(float4*)(tp + 0)  = make_float4(0, 0, 0, 0);
        *(float4*)(tp + 4)  = make_float4(0, 0, 0, 0);
        *(float4*)(tp + 8)  = make_float4(0, 0, 0, 0);
        *(float4*)(tp + 12) = make_float4(0, 0, 0, 0);
        tp[0] = 1.0f;
    }
    __syncthreads();

    run_layer_ns<NG2>(smu + O_MIDN, RS2, g_wf5 + 32 * warp + lane, acc, r4, c);

    // h_out = h + acc
    #pragma unroll
    for (int mt = 0; mt < 4; mt++) {
        int nlo = n0b + mt * 16 + r4, nhi = nlo + 8;
        #pragma unroll
        for (int nt = 0; nt < 2; nt++) {
            int n0 = warp * 16 + nt * 8 + 2 * c;
            if (nlo < NODES) {
                float2 hv = *(const float2*)(h + (long long)nlo * D + n0);
                *(float2*)(h_out + (long long)nlo * D + n0) =
                    make_float2(hv.x + acc[mt][nt][0], hv.y + acc[mt][nt][1]);
            }
            if (nhi < NODES) {
                float2 hv = *(const float2*)(h + (long long)nhi * D + n0);
                *(float2*)(h_out + (long long)nhi * D + n0) =
                    make_float2(hv.x + acc[mt][nt][2], hv.y + acc[mt][nt][3]);
            }
        }
    }

    // coord_out = coord + clip(mean(trans))
    if (tid < TN) {
        int n = n0b + tid;
        if (n < NODES) {
            float cden = fmaxf(g_cnt[n], 1.0f);
            #pragma unroll
            for (int d3 = 0; d3 < 3; d3++) {
                float a = g_ts[n * 3 + d3] / cden;
                a = fminf(fmaxf(a, -MAXT), MAXT);
                coord_out[n * 3 + d3] = coord[n * 3 + d3] + a;
            }
        }
    }
}

// ---------------- launch ----------------
extern "C" void kernel_launch(void* const* d_in, const int* in_sizes, int n_in,
                              void* d_out, int out_size)
{
    const float* h     = (const float*)d_in[0];
    const int*   ei    = (const int*)d_in[1];
    const float* coord = (const float*)d_in[2];
    const float* We1   = (const float*)d_in[3];
    const float* be1   = (const float*)d_in[4];
    const float* We2   = (const float*)d_in[5];
    const float* be2   = (const float*)d_in[6];
    const float* Watt  = (const float*)d_in[7];
    const float* batt  = (const float*)d_in[8];
    const float* Wc1   = (const float*)d_in[9];
    const float* bc1   = (const float*)d_in[10];
    const float* Wc2   = (const float*)d_in[11];
    const float* Wn1   = (const float*)d_in[12];
    const float* bn1   = (const float*)d_in[13];
    const float* Wn2   = (const float*)d_in[14];
    const float* bn2   = (const float*)d_in[15];

    float* out       = (float*)d_out;
    float* h_out     = out;
    float* coord_out = out + (size_t)NODES * D;
    float* edge_out  = coord_out + (size_t)NODES * 3;

    size_t esm = (size_t)ESM_WORDS * sizeof(uint32_t);
    size_t nsm = (size_t)NSM_WORDS * sizeof(uint32_t);

    cudaFuncSetAttribute(edge_kernel, cudaFuncAttributeMaxDynamicSharedMemorySize, (int)esm);
    cudaFuncSetAttribute(node_kernel, cudaFuncAttributeMaxDynamicSharedMemorySize, (int)nsm);

    zero_kernel<<<512, 256>>>();
    int prep_threads = 2 * NKS1 * 8 * 32 + 3 * NKS2 * 8 * 32;
    prep_kernel<<<(prep_threads + 255) / 256, 256>>>(
        We1, be1, We2, be2, Wc1, bc1, Wn1, bn1, Wn2, bn2);
    edge_kernel<<<(EDGES + TE - 1) / TE, NTH, esm>>>(h, ei, coord, Watt, batt, Wc2, edge_out);
    node_kernel<<<(NODES + TN - 1) / TN, NTH, nsm>>>(h, coord, h_out, coord_out);
}

// round 11
// speedup vs baseline: 1.1097x; 1.1097x over previous
#include <cuda_runtime.h>
#include <stdint.h>

#define D 128
#define NODES 50000
#define EDGES 500000
#define MAXT 10.0f

#define TE 64
#define NTH 256
#define RS1 268          // K-dim stride (264 cols used; mod32=12 -> conflict-free)
#define RS2 140          // (136 cols used; mod32=12)
#define NKS1 33          // K=264/8
#define NKS2 17          // K=136/8

// ---------------- device scratch ----------------
__device__ float g_agg[(size_t)NODES * D];
__device__ float g_ts[(size_t)NODES * 3];
__device__ float g_cnt[NODES];
__device__ float4 g_wf1[NKS1 * 8 * 32];   // We1+be1 fragments
__device__ float4 g_wf2[NKS2 * 8 * 32];   // We2+be2
__device__ float4 g_wf3[NKS2 * 8 * 32];   // Wc1+bc1
__device__ float4 g_wf4[NKS1 * 8 * 32];   // Wn1+bn1
__device__ float4 g_wf5[NKS2 * 8 * 32];   // Wn2+bn2

// ---------------- helpers ----------------
__device__ __forceinline__ float silu_f(float x) {
    return x * __fdividef(1.0f, 1.0f + __expf(-x));
}
__device__ __forceinline__ float sigmoid_f(float x) {
    return __fdividef(1.0f, 1.0f + __expf(-x));
}
__device__ __forceinline__ float clampt(float x) {
    return fminf(fmaxf(x, -MAXT), MAXT);
}
__device__ __forceinline__ uint32_t tfbits(float x) {
    uint32_t u; asm("cvt.rna.tf32.f32 %0, %1;" : "=r"(u) : "f"(x)); return u;
}
__device__ __forceinline__ float tf32r(float x) { return __uint_as_float(tfbits(x)); }

__device__ __forceinline__ void red2(float* p, float a, float b) {
    asm volatile("red.global.add.v2.f32 [%0], {%1, %2};"
                 :: "l"(p), "f"(a), "f"(b) : "memory");
}

__device__ __forceinline__ void mma8(float acc[4],
    uint32_t a0, uint32_t a1, uint32_t a2, uint32_t a3, uint32_t b0, uint32_t b1)
{
    asm volatile(
        "mma.sync.aligned.m16n8k8.row.col.f32.tf32.tf32.f32 "
        "{%0,%1,%2,%3}, {%4,%5,%6,%7}, {%8,%9}, {%0,%1,%2,%3};"
        : "+f"(acc[0]), "+f"(acc[1]), "+f"(acc[2]), "+f"(acc[3])
        : "r"(a0), "r"(a1), "r"(a2), "r"(a3), "r"(b0), "r"(b1));
}

__device__ __forceinline__ void ldsm4(uint32_t a[4], uint32_t addr) {
    asm volatile("ldmatrix.sync.aligned.m8n8.x4.shared.b16 {%0,%1,%2,%3}, [%4];"
        : "=r"(a[0]), "=r"(a[1]), "=r"(a[2]), "=r"(a[3]) : "r"(addr));
}

// Warp computes: acc[mt][nt] = A[all 64 rows] @ B[this warp's 16 cols]
// abase = per-thread ldmatrix address (smem u32); rsb = row stride in bytes
template<int NKS>
__device__ __forceinline__ void run_layer_ns(
    uint32_t abase, int rsb,
    const float4* __restrict__ wq,
    float acc[4][2][4])
{
    #pragma unroll 2
    for (int ks = 0; ks < NKS; ks++) {
        float4 b0 = wq[ks * 256];
        #pragma unroll
        for (int mt = 0; mt < 4; mt++) {
            uint32_t a[4];
            ldsm4(a, abase + mt * 16 * rsb + ks * 32);
            mma8(acc[mt][0], a[0], a[1], a[2], a[3],
                 __float_as_uint(b0.x), __float_as_uint(b0.y));
            mma8(acc[mt][1], a[0], a[1], a[2], a[3],
                 __float_as_uint(b0.z), __float_as_uint(b0.w));
        }
    }
}

// ---------------- zero + weight prep ----------------
__global__ void zero_kernel() {
    int idx = blockIdx.x * blockDim.x + threadIdx.x;
    int stride = gridDim.x * blockDim.x;
    for (int i = idx; i < NODES * D; i += stride) g_agg[i] = 0.0f;
    for (int i = idx; i < NODES * 3; i += stride) g_ts[i] = 0.0f;
    for (int i = idx; i < NODES; i += stride) g_cnt[i] = 0.0f;
}

__device__ __forceinline__ float wb(const float* W, const float* b, int K, int k, int n) {
    if (k < K) return W[k * D + n];
    if (k == K) return b[n];
    return 0.0f;
}

__global__ void prep_kernel(
    const float* __restrict__ We1, const float* __restrict__ be1,
    const float* __restrict__ We2, const float* __restrict__ be2,
    const float* __restrict__ Wc1, const float* __restrict__ bc1,
    const float* __restrict__ Wn1, const float* __restrict__ bn1,
    const float* __restrict__ Wn2, const float* __restrict__ bn2)
{
    int t = blockIdx.x * blockDim.x + threadIdx.x;
    const int n1 = NKS1 * 8 * 32, n2 = NKS2 * 8 * 32;
    const float *W, *bi; int K; float4* dst; int idx;
    if (t < n1)                    { W = We1; bi = be1; K = 257; dst = g_wf1; idx = t; }
    else if (t < n1 + n2)          { W = We2; bi = be2; K = 128; dst = g_wf2; idx = t - n1; }
    else if (t < n1 + 2 * n2)      { W = Wc1; bi = bc1; K = 128; dst = g_wf3; idx = t - n1 - n2; }
    else if (t < 2 * n1 + 2 * n2)  { W = Wn1; bi = bn1; K = 256; dst = g_wf4; idx = t - n1 - 2 * n2; }
    else if (t < 2 * n1 + 3 * n2)  { W = Wn2; bi = bn2; K = 128; dst = g_wf5; idx = t - 2 * n1 - 2 * n2; }
    else return;
    int lane = idx & 31, p = (idx >> 5) & 7, ks = idx >> 8;
    int c = lane & 3, r = lane >> 2, k0 = ks * 8;
    float4 v;
    v.x = tf32r(wb(W, bi, K, k0 + c,     p * 16 + r));
    v.y = tf32r(wb(W, bi, K, k0 + 4 + c, p * 16 + r));
    v.z = tf32r(wb(W, bi, K, k0 + c,     p * 16 + 8 + r));
    v.w = tf32r(wb(W, bi, K, k0 + 4 + c, p * 16 + 8 + r));
    dst[idx] = v;
}

// ---------------- edge kernel ----------------
#define O_SA    0
#define O_SMID  (TE * RS1)                   // 17152
#define O_SCD   (O_SMID + TE * RS2)          // 26112
#define O_ATTP  (O_SCD + TE * 4)             // 26368  [8][64]
#define O_CWP   (O_ATTP + 8 * TE)            // 26880  [8][64]
#define O_SATT  (O_CWP + 8 * TE)             // 27392
#define O_SROW  (O_SATT + TE)                // 27456
#define O_SCOL  (O_SROW + TE)                // 27520
#define ESM_WORDS (O_SCOL + TE)              // 27584 words = 110336 B -> 2 CTA/SM
#define O_SEF   O_SA                         // reuse sA region with stride RS2

__global__ void __launch_bounds__(NTH) edge_kernel(
    const float* __restrict__ h, const int* __restrict__ ei,
    const float* __restrict__ coord,
    const float* __restrict__ Watt, const float* __restrict__ batt,
    const float* __restrict__ Wc2,
    float* __restrict__ edge_out)
{
    extern __shared__ uint32_t smu[];
    float* smf = (float*)smu;
    int*   sRow = (int*)(smu + O_SROW);
    int*   sCol = (int*)(smu + O_SCOL);

    const int tid  = threadIdx.x;
    const int lane = tid & 31;
    const int warp = tid >> 5;      // 0..7 = N-slice (16 cols)
    const int c    = lane & 3;
    const int r4   = lane >> 2;
    const long long e0 = (long long)blockIdx.x * TE;
    // ldmatrix per-thread address pieces
    const int ltile = lane >> 3, li = lane & 7;
    const int lrow  = (ltile & 1) * 8 + li;        // row within 16-row tile
    const int lcol  = (ltile >> 1) * 16;           // byte offset (cols 4-7)
    const uint32_t smb = (uint32_t)__cvta_generic_to_shared(smu);
    const uint32_t aA   = smb + (O_SA   * 4) + lrow * (RS1 * 4) + lcol;
    const uint32_t aMID = smb + (O_SMID * 4) + lrow * (RS2 * 4) + lcol;
    const uint32_t aEF  = smb + (O_SEF  * 4) + lrow * (RS2 * 4) + lcol;

    // ---- indices, coord_diff, radial/bias tail cols ----
    if (tid < TE) {
        int el = tid;
        long long e = e0 + el;
        int rr = 0, cc = 0; float dx = 0, dy = 0, dz = 0, rad = 0;
        if (e < EDGES) {
            rr = ei[e]; cc = ei[(long long)EDGES + e];
            dx = coord[rr * 3 + 0] - coord[cc * 3 + 0];
            dy = coord[rr * 3 + 1] - coord[cc * 3 + 1];
            dz = coord[rr * 3 + 2] - coord[cc * 3 + 2];
            rad = dx * dx + dy * dy + dz * dz;
        }
        sRow[el] = rr; sCol[el] = cc;
        smf[O_SCD + el * 4 + 0] = dx;
        smf[O_SCD + el * 4 + 1] = dy;
        smf[O_SCD + el * 4 + 2] = dz;
        *(float4*)(smf + O_SA + el * RS1 + 256) = make_float4(tf32r(rad), 1.0f, 0.0f, 0.0f);
        *(float4*)(smf + O_SA + el * RS1 + 260) = make_float4(0.0f, 0.0f, 0.0f, 0.0f);
    }
    __syncthreads();

    // ---- gather h[row], h[col] -> sA (tf32), warp w fills rows w*8..+8 ----
    for (int i = 0; i < 8; i++) {
        int el = warp * 8 + i;
        int rr = sRow[el], cc = sCol[el];
        float4 v = *(const float4*)(h + (long long)rr * D + lane * 4);
        float4 w = *(const float4*)(h + (long long)cc * D + lane * 4);
        *(float4*)(smf + O_SA + el * RS1 + lane * 4) =
            make_float4(tf32r(v.x), tf32r(v.y), tf32r(v.z), tf32r(v.w));
        *(float4*)(smf + O_SA + el * RS1 + 128 + lane * 4) =
            make_float4(tf32r(w.x), tf32r(w.y), tf32r(w.z), tf32r(w.w));
    }
    __syncthreads();

    float acc[4][2][4];
    #pragma unroll
    for (int m = 0; m < 4; m++)
        #pragma unroll
        for (int n = 0; n < 2; n++)
            { acc[m][n][0]=0; acc[m][n][1]=0; acc[m][n][2]=0; acc[m][n][3]=0; }

    // ================= Layer 1 =================
    run_layer_ns<NKS1>(aA, RS1 * 4, g_wf1 + 32 * warp + lane, acc);

    #pragma unroll
    for (int mt = 0; mt < 4; mt++) {
        int rlo = mt * 16 + r4;
        #pragma unroll
        for (int nt = 0; nt < 2; nt++) {
            int n0 = warp * 16 + nt * 8 + 2 * c;
            *(uint2*)(smu + O_SMID + rlo * RS2 + n0) =
                make_uint2(tfbits(silu_f(acc[mt][nt][0])), tfbits(silu_f(acc[mt][nt][1])));
            *(uint2*)(smu + O_SMID + (rlo + 8) * RS2 + n0) =
                make_uint2(tfbits(silu_f(acc[mt][nt][2])), tfbits(silu_f(acc[mt][nt][3])));
            acc[mt][nt][0]=0; acc[mt][nt][1]=0; acc[mt][nt][2]=0; acc[mt][nt][3]=0;
        }
    }
    if (tid < TE) {
        *(float4*)(smf + O_SMID + tid * RS2 + 128) = make_float4(1.0f, 0, 0, 0);
        *(float4*)(smf + O_SMID + tid * RS2 + 132) = make_float4(0, 0, 0, 0);
    }
    __syncthreads();

    // ================= Layer 2 =================
    run_layer_ns<NKS2>(aMID, RS2 * 4, g_wf2 + 32 * warp + lane, acc);

    // attention partials (keep silu'd values in acc)
    {
        float plo[4] = {0,0,0,0}, phi[4] = {0,0,0,0};
        #pragma unroll
        for (int mt = 0; mt < 4; mt++) {
            #pragma unroll
            for (int nt = 0; nt < 2; nt++) {
                int n0 = warp * 16 + nt * 8 + 2 * c;
                float2 wa = *(const float2*)(Watt + n0);
                acc[mt][nt][0] = silu_f(acc[mt][nt][0]);
                acc[mt][nt][1] = silu_f(acc[mt][nt][1]);
                acc[mt][nt][2] = silu_f(acc[mt][nt][2]);
                acc[mt][nt][3] = silu_f(acc[mt][nt][3]);
                plo[mt] += acc[mt][nt][0] * wa.x + acc[mt][nt][1] * wa.y;
                phi[mt] += acc[mt][nt][2] * wa.x + acc[mt][nt][3] * wa.y;
            }
        }
        #pragma unroll
        for (int mt = 0; mt < 4; mt++) {
            plo[mt] += __shfl_xor_sync(0xffffffffu, plo[mt], 1);
            plo[mt] += __shfl_xor_sync(0xffffffffu, plo[mt], 2);
            phi[mt] += __shfl_xor_sync(0xffffffffu, phi[mt], 1);
            phi[mt] += __shfl_xor_sync(0xffffffffu, phi[mt], 2);
        }
        if (c == 0) {
            #pragma unroll
            for (int mt = 0; mt < 4; mt++) {
                smf[O_ATTP + warp * 64 + mt * 16 + r4]     = plo[mt];
                smf[O_ATTP + warp * 64 + mt * 16 + 8 + r4] = phi[mt];
            }
        }
    }
    __syncthreads();
    if (tid < TE) {
        float s = 0.0f;
        #pragma unroll
        for (int w = 0; w < 8; w++) s += smf[O_ATTP + w * 64 + tid];
        smf[O_SATT + tid] = sigmoid_f(s + batt[0]);
    }
    __syncthreads();

    // apply attention: edge_out + agg red.v2 + sEf (tf32, for layer 3)
    #pragma unroll
    for (int mt = 0; mt < 4; mt++) {
        int elo = mt * 16 + r4, ehi = elo + 8;
        float attlo = smf[O_SATT + elo], atthi = smf[O_SATT + ehi];
        bool vlo = (e0 + elo) < EDGES, vhi = (e0 + ehi) < EDGES;
        long long glo = (long long)sRow[elo] * D;
        long long ghi = (long long)sRow[ehi] * D;
        float* out_lo = edge_out + (e0 + elo) * D;
        float* out_hi = edge_out + (e0 + ehi) * D;
        #pragma unroll
        for (int nt = 0; nt < 2; nt++) {
            int n0 = warp * 16 + nt * 8 + 2 * c;
            float f0 = acc[mt][nt][0] * attlo, f1 = acc[mt][nt][1] * attlo;
            float f2 = acc[mt][nt][2] * atthi, f3 = acc[mt][nt][3] * atthi;
            if (vlo) {
                *(float2*)(out_lo + n0) = make_float2(f0, f1);
                red2(g_agg + glo + n0, f0, f1);
            }
            if (vhi) {
                *(float2*)(out_hi + n0) = make_float2(f2, f3);
                red2(g_agg + ghi + n0, f2, f3);
            }
            *(uint2*)(smu + O_SEF + elo * RS2 + n0) = make_uint2(tfbits(f0), tfbits(f1));
            *(uint2*)(smu + O_SEF + ehi * RS2 + n0) = make_uint2(tfbits(f2), tfbits(f3));
            acc[mt][nt][0]=0; acc[mt][nt][1]=0; acc[mt][nt][2]=0; acc[mt][nt][3]=0;
        }
    }
    if (tid < TE) {
        *(float4*)(smf + O_SEF + tid * RS2 + 128) = make_float4(1.0f, 0, 0, 0);
        *(float4*)(smf + O_SEF + tid * RS2 + 132) = make_float4(0, 0, 0, 0);
    }
    __syncthreads();

    // ================= Layer 3 (coord MLP) =================
    run_layer_ns<NKS2>(aEF, RS2 * 4, g_wf3 + 32 * warp + lane, acc);
    {
        float qlo[4] = {0,0,0,0}, qhi[4] = {0,0,0,0};
        #pragma unroll
        for (int mt = 0; mt < 4; mt++) {
            #pragma unroll
            for (int nt = 0; nt < 2; nt++) {
                int n0 = warp * 16 + nt * 8 + 2 * c;
                float2 w2 = *(const float2*)(Wc2 + n0);
                qlo[mt] += silu_f(acc[mt][nt][0]) * w2.x + silu_f(acc[mt][nt][1]) * w2.y;
                qhi[mt] += silu_f(acc[mt][nt][2]) * w2.x + silu_f(acc[mt][nt][3]) * w2.y;
            }
        }
        #pragma unroll
        for (int mt = 0; mt < 4; mt++) {
            qlo[mt] += __shfl_xor_sync(0xffffffffu, qlo[mt], 1);
            qlo[mt] += __shfl_xor_sync(0xffffffffu, qlo[mt], 2);
            qhi[mt] += __shfl_xor_sync(0xffffffffu, qhi[mt], 1);
            qhi[mt] += __shfl_xor_sync(0xffffffffu, qhi[mt], 2);
        }
        if (c == 0) {
            #pragma unroll
            for (int mt = 0; mt < 4; mt++) {
                smf[O_CWP + warp * 64 + mt * 16 + r4]     = qlo[mt];
                smf[O_CWP + warp * 64 + mt * 16 + 8 + r4] = qhi[mt];
            }
        }
    }
    __syncthreads();
    if (tid < TE && (e0 + tid) < EDGES) {
        float cw = 0.0f;
        #pragma unroll
        for (int w = 0; w < 8; w++) cw += smf[O_CWP + w * 64 + tid];
        int n = sRow[tid];
        atomicAdd(g_ts + n * 3 + 0, clampt(smf[O_SCD + tid * 4 + 0] * cw));
        atomicAdd(g_ts + n * 3 + 1, clampt(smf[O_SCD + tid * 4 + 1] * cw));
        atomicAdd(g_ts + n * 3 + 2, clampt(smf[O_SCD + tid * 4 + 2] * cw));
        atomicAdd(g_cnt + n, 1.0f);
    }
}

// ---------------- node kernel ----------------
#define TN 64
#define O_XN    0
#define O_MIDN  (TN * RS1)                   // 17152
#define NSM_WORDS (O_MIDN + TN * RS2)        // 26112 words = 104448 B -> 2 CTA/SM

__global__ void __launch_bounds__(NTH) node_kernel(
    const float* __restrict__ h, const float* __restrict__ coord,
    float* __restrict__ h_out, float* __restrict__ coord_out)
{
    extern __shared__ uint32_t smu[];
    float* smf = (float*)smu;

    const int tid  = threadIdx.x;
    const int lane = tid & 31;
    const int warp = tid >> 5;
    const int c    = lane & 3;
    const int r4   = lane >> 2;
    const int n0b  = blockIdx.x * TN;
    const int ltile = lane >> 3, li = lane & 7;
    const int lrow  = (ltile & 1) * 8 + li;
    const int lcol  = (ltile >> 1) * 16;
    const uint32_t smb = (uint32_t)__cvta_generic_to_shared(smu);
    const uint32_t aXN   = smb + (O_XN   * 4) + lrow * (RS1 * 4) + lcol;
    const uint32_t aMIDN = smb + (O_MIDN * 4) + lrow * (RS2 * 4) + lcol;

    // gather [h | agg] -> sXN (tf32), warp w fills rows w*8..+8
    for (int i = 0; i < 8; i++) {
        int row = warp * 8 + i;
        int n = n0b + row;
        float4 tv = make_float4(0, 0, 0, 0), tw = make_float4(0, 0, 0, 0);
        if (n < NODES) {
            float4 v = *(const float4*)(h + (long long)n * D + lane * 4);
            float4 w = *(const float4*)(g_agg + (long long)n * D + lane * 4);
            tv = make_float4(tf32r(v.x), tf32r(v.y), tf32r(v.z), tf32r(v.w));
            tw = make_float4(tf32r(w.x), tf32r(w.y), tf32r(w.z), tf32r(w.w));
        }
        *(float4*)(smf + O_XN + row * RS1 + lane * 4) = tv;
        *(float4*)(smf + O_XN + row * RS1 + 128 + lane * 4) = tw;
    }
    if (tid < TN) {
        *(float4*)(smf + O_XN + tid * RS1 + 256) = make_float4(1.0f, 0, 0, 0);
        *(float4*)(smf + O_XN + tid * RS1 + 260) = make_float4(0, 0, 0, 0);
    }
    __syncthreads();

    float acc[4][2][4];
    #pragma unroll
    for (int m = 0; m < 4; m++)
        #pragma unroll
        for (int n = 0; n < 2; n++)
            { acc[m][n][0]=0; acc[m][n][1]=0; acc[m][n][2]=0; acc[m][n][3]=0; }

    run_layer_ns<NKS1>(aXN, RS1 * 4, g_wf4 + 32 * warp + lane, acc);

    #pragma unroll
    for (int mt = 0; mt < 4; mt++) {
        int rlo = mt * 16 + r4;
        #pragma unroll
        for (int nt = 0; nt < 2; nt++) {
            int n0 = warp * 16 + nt * 8 + 2 * c;
            *(uint2*)(smu + O_MIDN + rlo * RS2 + n0) =
                make_uint2(tfbits(silu_f(acc[mt][nt][0])), tfbits(silu_f(acc[mt][nt][1])));
            *(uint2*)(smu + O_MIDN + (rlo + 8) * RS2 + n0) =
                make_uint2(tfbits(silu_f(acc[mt][nt][2])), tfbits(silu_f(acc[mt][nt][3])));
            acc[mt][nt][0]=0; acc[mt][nt][1]=0; acc[mt][nt][2]=0; acc[mt][nt][3]=0;
        }
    }
    if (tid < TN) {
        *(float4*)(smf + O_MIDN + tid * RS2 + 128) = make_float4(1.0f, 0, 0, 0);
        *(float4*)(smf + O_MIDN + tid * RS2 + 132) = make_float4(0, 0, 0, 0);
    }
    __syncthreads();

    run_layer_ns<NKS2>(aMIDN, RS2 * 4, g_wf5 + 32 * warp + lane, acc);

    // h_out = h + acc
    #pragma unroll
    for (int mt = 0; mt < 4; mt++) {
        int nlo = n0b + mt * 16 + r4, nhi = nlo + 8;
        #pragma unroll
        for (int nt = 0; nt < 2; nt++) {
            int n0 = warp * 16 + nt * 8 + 2 * c;
            if (nlo < NODES) {
                float2 hv = *(const float2*)(h + (long long)nlo * D + n0);
                *(float2*)(h_out + (long long)nlo * D + n0) =
                    make_float2(hv.x + acc[mt][nt][0], hv.y + acc[mt][nt][1]);
            }
            if (nhi < NODES) {
                float2 hv = *(const float2*)(h + (long long)nhi * D + n0);
                *(float2*)(h_out + (long long)nhi * D + n0) =
                    make_float2(hv.x + acc[mt][nt][2], hv.y + acc[mt][nt][3]);
            }
        }
    }

    // coord_out = coord + clip(mean(trans))
    if (tid < TN) {
        int n = n0b + tid;
        if (n < NODES) {
            float cden = fmaxf(g_cnt[n], 1.0f);
            #pragma unroll
            for (int d3 = 0; d3 < 3; d3++) {
                float a = g_ts[n * 3 + d3] / cden;
                a = fminf(fmaxf(a, -MAXT), MAXT);
                coord_out[n * 3 + d3] = coord[n * 3 + d3] + a;
            }
        }
    }
}

// ---------------- launch ----------------
extern "C" void kernel_launch(void* const* d_in, const int* in_sizes, int n_in,
                              void* d_out, int out_size)
{
    const float* h     = (const float*)d_in[0];
    const int*   ei    = (const int*)d_in[1];
    const float* coord = (const float*)d_in[2];
    const float* We1   = (const float*)d_in[3];
    const float* be1   = (const float*)d_in[4];
    const float* We2   = (const float*)d_in[5];
    const float* be2   = (const float*)d_in[6];
    const float* Watt  = (const float*)d_in[7];
    const float* batt  = (const float*)d_in[8];
    const float* Wc1   = (const float*)d_in[9];
    const float* bc1   = (const float*)d_in[10];
    const float* Wc2   = (const float*)d_in[11];
    const float* Wn1   = (const float*)d_in[12];
    const float* bn1   = (const float*)d_in[13];
    const float* Wn2   = (const float*)d_in[14];
    const float* bn2   = (const float*)d_in[15];

    float* out       = (float*)d_out;
    float* h_out     = out;
    float* coord_out = out + (size_t)NODES * D;
    float* edge_out  = coord_out + (size_t)NODES * 3;

    size_t esm = (size_t)ESM_WORDS * sizeof(uint32_t);
    size_t nsm = (size_t)NSM_WORDS * sizeof(uint32_t);

    cudaFuncSetAttribute(edge_kernel, cudaFuncAttributeMaxDynamicSharedMemorySize, (int)esm);
    cudaFuncSetAttribute(node_kernel, cudaFuncAttributeMaxDynamicSharedMemorySize, (int)nsm);

    zero_kernel<<<512, 256>>>();
    int prep_threads = 2 * NKS1 * 8 * 32 + 3 * NKS2 * 8 * 32;
    prep_kernel<<<(prep_threads + 255) / 256, 256>>>(
        We1, be1, We2, be2, Wc1, bc1, Wn1, bn1, Wn2, bn2);
    edge_kernel<<<(EDGES + TE - 1) / TE, NTH, esm>>>(h, ei, coord, Watt, batt, Wc2, edge_out);
    node_kernel<<<(NODES + TN - 1) / TN, NTH, nsm>>>(h, coord, h_out, coord_out);
}

// round 14
// speedup vs baseline: 1.1860x; 1.0688x over previous
#include <cuda_runtime.h>
#include <stdint.h>

#define D 128
#define NODES 50000
#define EDGES 500000
#define MAXT 10.0f

#define TE 32
#define NTH 256
#define RS1 268          // K-dim stride (264 cols used; mod32=12 -> conflict-free)
#define RS2 140          // (136 cols used; mod32=12)
#define NKS1 33          // K=264/8
#define NKS2 17          // K=136/8

// ---------------- device scratch ----------------
__device__ float g_agg[(size_t)NODES * D];
__device__ float g_ts[(size_t)NODES * 3];
__device__ float g_cnt[NODES];
__device__ float4 g_wf1[NKS1 * 8 * 32];   // We1+be1 fragments
__device__ float4 g_wf2[NKS2 * 8 * 32];   // We2+be2
__device__ float4 g_wf3[NKS2 * 8 * 32];   // Wc1+bc1
__device__ float4 g_wf4[NKS1 * 8 * 32];   // Wn1+bn1
__device__ float4 g_wf5[NKS2 * 8 * 32];   // Wn2+bn2

// ---------------- helpers ----------------
__device__ __forceinline__ float silu_f(float x) {
    return x * __fdividef(1.0f, 1.0f + __expf(-x));
}
__device__ __forceinline__ float sigmoid_f(float x) {
    return __fdividef(1.0f, 1.0f + __expf(-x));
}
__device__ __forceinline__ float clampt(float x) {
    return fminf(fmaxf(x, -MAXT), MAXT);
}
__device__ __forceinline__ uint32_t tfbits(float x) {
    uint32_t u; asm("cvt.rna.tf32.f32 %0, %1;" : "=r"(u) : "f"(x)); return u;
}
__device__ __forceinline__ float tf32r(float x) { return __uint_as_float(tfbits(x)); }

__device__ __forceinline__ void red2(float* p, float a, float b) {
    asm volatile("red.global.add.v2.f32 [%0], {%1, %2};"
                 :: "l"(p), "f"(a), "f"(b) : "memory");
}

__device__ __forceinline__ void mma8(float acc[4],
    uint32_t a0, uint32_t a1, uint32_t a2, uint32_t a3, uint32_t b0, uint32_t b1)
{
    asm volatile(
        "mma.sync.aligned.m16n8k8.row.col.f32.tf32.tf32.f32 "
        "{%0,%1,%2,%3}, {%4,%5,%6,%7}, {%8,%9}, {%0,%1,%2,%3};"
        : "+f"(acc[0]), "+f"(acc[1]), "+f"(acc[2]), "+f"(acc[3])
        : "r"(a0), "r"(a1), "r"(a2), "r"(a3), "r"(b0), "r"(b1));
}

__device__ __forceinline__ void ldsm4(uint32_t a[4], uint32_t addr) {
    asm volatile("ldmatrix.sync.aligned.m8n8.x4.shared.b16 {%0,%1,%2,%3}, [%4];"
        : "=r"(a[0]), "=r"(a[1]), "=r"(a[2]), "=r"(a[3]) : "r"(addr));
}

// Warp computes: acc[mt][nt] = A[all 32 rows] @ B[this warp's 16 cols]
template<int NKS>
__device__ __forceinline__ void run_layer_ns(
    uint32_t abase, int rsb,
    const float4* __restrict__ wq,
    float acc[2][2][4])
{
    #pragma unroll 2
    for (int ks = 0; ks < NKS; ks++) {
        float4 b0 = wq[ks * 256];
        #pragma unroll
        for (int mt = 0; mt < 2; mt++) {
            uint32_t a[4];
            ldsm4(a, abase + mt * 16 * rsb + ks * 32);
            mma8(acc[mt][0], a[0], a[1], a[2], a[3],
                 __float_as_uint(b0.x), __float_as_uint(b0.y));
            mma8(acc[mt][1], a[0], a[1], a[2], a[3],
                 __float_as_uint(b0.z), __float_as_uint(b0.w));
        }
    }
}

// ---------------- zero + weight prep ----------------
__global__ void zero_kernel() {
    int idx = blockIdx.x * blockDim.x + threadIdx.x;
    int stride = gridDim.x * blockDim.x;
    for (int i = idx; i < NODES * D; i += stride) g_agg[i] = 0.0f;
    for (int i = idx; i < NODES * 3; i += stride) g_ts[i] = 0.0f;
    for (int i = idx; i < NODES; i += stride) g_cnt[i] = 0.0f;
}

__device__ __forceinline__ float wb(const float* W, const float* b, int K, int k, int n) {
    if (k < K) return W[k * D + n];
    if (k == K) return b[n];
    return 0.0f;
}

__global__ void prep_kernel(
    const float* __restrict__ We1, const float* __restrict__ be1,
    const float* __restrict__ We2, const float* __restrict__ be2,
    const float* __restrict__ Wc1, const float* __restrict__ bc1,
    const float* __restrict__ Wn1, const float* __restrict__ bn1,
    const float* __restrict__ Wn2, const float* __restrict__ bn2)
{
    int t = blockIdx.x * blockDim.x + threadIdx.x;
    const int n1 = NKS1 * 8 * 32, n2 = NKS2 * 8 * 32;
    const float *W, *bi; int K; float4* dst; int idx;
    if (t < n1)                    { W = We1; bi = be1; K = 257; dst = g_wf1; idx = t; }
    else if (t < n1 + n2)          { W = We2; bi = be2; K = 128; dst = g_wf2; idx = t - n1; }
    else if (t < n1 + 2 * n2)      { W = Wc1; bi = bc1; K = 128; dst = g_wf3; idx = t - n1 - n2; }
    else if (t < 2 * n1 + 2 * n2)  { W = Wn1; bi = bn1; K = 256; dst = g_wf4; idx = t - n1 - 2 * n2; }
    else if (t < 2 * n1 + 3 * n2)  { W = Wn2; bi = bn2; K = 128; dst = g_wf5; idx = t - 2 * n1 - 2 * n2; }
    else return;
    int lane = idx & 31, p = (idx >> 5) & 7, ks = idx >> 8;
    int c = lane & 3, r = lane >> 2, k0 = ks * 8;
    float4 v;
    v.x = tf32r(wb(W, bi, K, k0 + c,     p * 16 + r));
    v.y = tf32r(wb(W, bi, K, k0 + 4 + c, p * 16 + r));
    v.z = tf32r(wb(W, bi, K, k0 + c,     p * 16 + 8 + r));
    v.w = tf32r(wb(W, bi, K, k0 + 4 + c, p * 16 + 8 + r));
    dst[idx] = v;
}

// ---------------- edge kernel ----------------
#define O_SA    0
#define O_SMID  (TE * RS1)                   // 8576
#define O_SCD   (O_SMID + TE * RS2)          // 13056
#define O_ATTP  (O_SCD + TE * 4)             // 13184  [8][32]
#define O_CWP   (O_ATTP + 8 * TE)            // 13440  [8][32]
#define O_SATT  (O_CWP + 8 * TE)             // 13696
#define O_SROW  (O_SATT + TE)                // 13728
#define O_SCOL  (O_SROW + TE)                // 13760
#define ESM_WORDS (O_SCOL + TE)              // 13792 words = 55168 B -> 4 CTA/SM
#define O_SEF   O_SA                         // reuse sA region with stride RS2

__global__ void __launch_bounds__(NTH) edge_kernel(
    const float* __restrict__ h, const int* __restrict__ ei,
    const float* __restrict__ coord,
    const float* __restrict__ Watt, const float* __restrict__ batt,
    const float* __restrict__ Wc2,
    float* __restrict__ edge_out)
{
    extern __shared__ uint32_t smu[];
    float* smf = (float*)smu;
    int*   sRow = (int*)(smu + O_SROW);
    int*   sCol = (int*)(smu + O_SCOL);

    const int tid  = threadIdx.x;
    const int lane = tid & 31;
    const int warp = tid >> 5;      // 0..7 = N-slice (16 cols)
    const int c    = lane & 3;
    const int r4   = lane >> 2;
    const long long e0 = (long long)blockIdx.x * TE;
    // ldmatrix per-thread address pieces
    const int ltile = lane >> 3, li = lane & 7;
    const int lrow  = (ltile & 1) * 8 + li;        // row within 16-row tile
    const int lcol  = (ltile >> 1) * 16;           // byte offset (cols 4-7)
    const uint32_t smb = (uint32_t)__cvta_generic_to_shared(smu);
    const uint32_t aA   = smb + (O_SA   * 4) + lrow * (RS1 * 4) + lcol;
    const uint32_t aMID = smb + (O_SMID * 4) + lrow * (RS2 * 4) + lcol;
    const uint32_t aEF  = smb + (O_SEF  * 4) + lrow * (RS2 * 4) + lcol;

    // ---- indices, coord_diff, radial/bias tail cols ----
    if (tid < TE) {
        int el = tid;
        long long e = e0 + el;
        int rr = 0, cc = 0; float dx = 0, dy = 0, dz = 0, rad = 0;
        if (e < EDGES) {
            rr = ei[e]; cc = ei[(long long)EDGES + e];
            dx = coord[rr * 3 + 0] - coord[cc * 3 + 0];
            dy = coord[rr * 3 + 1] - coord[cc * 3 + 1];
            dz = coord[rr * 3 + 2] - coord[cc * 3 + 2];
            rad = dx * dx + dy * dy + dz * dz;
        }
        sRow[el] = rr; sCol[el] = cc;
        smf[O_SCD + el * 4 + 0] = dx;
        smf[O_SCD + el * 4 + 1] = dy;
        smf[O_SCD + el * 4 + 2] = dz;
        *(float4*)(smf + O_SA + el * RS1 + 256) = make_float4(tf32r(rad), 1.0f, 0.0f, 0.0f);
        *(float4*)(smf + O_SA + el * RS1 + 260) = make_float4(0.0f, 0.0f, 0.0f, 0.0f);
    }
    __syncthreads();

    // ---- gather h[row], h[col] -> sA (tf32), warp w fills rows w*4..+4 ----
    for (int i = 0; i < 4; i++) {
        int el = warp * 4 + i;
        int rr = sRow[el], cc = sCol[el];
        float4 v = *(const float4*)(h + (long long)rr * D + lane * 4);
        float4 w = *(const float4*)(h + (long long)cc * D + lane * 4);
        *(float4*)(smf + O_SA + el * RS1 + lane * 4) =
            make_float4(tf32r(v.x), tf32r(v.y), tf32r(v.z), tf32r(v.w));
        *(float4*)(smf + O_SA + el * RS1 + 128 + lane * 4) =
            make_float4(tf32r(w.x), tf32r(w.y), tf32r(w.z), tf32r(w.w));
    }
    __syncthreads();

    float acc[2][2][4];
    #pragma unroll
    for (int m = 0; m < 2; m++)
        #pragma unroll
        for (int n = 0; n < 2; n++)
            { acc[m][n][0]=0; acc[m][n][1]=0; acc[m][n][2]=0; acc[m][n][3]=0; }

    // ================= Layer 1 =================
    run_layer_ns<NKS1>(aA, RS1 * 4, g_wf1 + 32 * warp + lane, acc);

    #pragma unroll
    for (int mt = 0; mt < 2; mt++) {
        int rlo = mt * 16 + r4;
        #pragma unroll
        for (int nt = 0; nt < 2; nt++) {
            int n0 = warp * 16 + nt * 8 + 2 * c;
            *(uint2*)(smu + O_SMID + rlo * RS2 + n0) =
                make_uint2(tfbits(silu_f(acc[mt][nt][0])), tfbits(silu_f(acc[mt][nt][1])));
            *(uint2*)(smu + O_SMID + (rlo + 8) * RS2 + n0) =
                make_uint2(tfbits(silu_f(acc[mt][nt][2])), tfbits(silu_f(acc[mt][nt][3])));
            acc[mt][nt][0]=0; acc[mt][nt][1]=0; acc[mt][nt][2]=0; acc[mt][nt][3]=0;
        }
    }
    if (tid < TE) {
        *(float4*)(smf + O_SMID + tid * RS2 + 128) = make_float4(1.0f, 0, 0, 0);
        *(float4*)(smf + O_SMID + tid * RS2 + 132) = make_float4(0, 0, 0, 0);
    }
    __syncthreads();

    // ================= Layer 2 =================
    run_layer_ns<NKS2>(aMID, RS2 * 4, g_wf2 + 32 * warp + lane, acc);

    // attention partials (keep silu'd values in acc)
    {
        float plo[2] = {0,0}, phi[2] = {0,0};
        #pragma unroll
        for (int mt = 0; mt < 2; mt++) {
            #pragma unroll
            for (int nt = 0; nt < 2; nt++) {
                int n0 = warp * 16 + nt * 8 + 2 * c;
                float2 wa = *(const float2*)(Watt + n0);
                acc[mt][nt][0] = silu_f(acc[mt][nt][0]);
                acc[mt][nt][1] = silu_f(acc[mt][nt][1]);
                acc[mt][nt][2] = silu_f(acc[mt][nt][2]);
                acc[mt][nt][3] = silu_f(acc[mt][nt][3]);
                plo[mt] += acc[mt][nt][0] * wa.x + acc[mt][nt][1] * wa.y;
                phi[mt] += acc[mt][nt][2] * wa.x + acc[mt][nt][3] * wa.y;
            }
        }
        #pragma unroll
        for (int mt = 0; mt < 2; mt++) {
            plo[mt] += __shfl_xor_sync(0xffffffffu, plo[mt], 1);
            plo[mt] += __shfl_xor_sync(0xffffffffu, plo[mt], 2);
            phi[mt] += __shfl_xor_sync(0xffffffffu, phi[mt], 1);
            phi[mt] += __shfl_xor_sync(0xffffffffu, phi[mt], 2);
        }
        if (c == 0) {
            #pragma unroll
            for (int mt = 0; mt < 2; mt++) {
                smf[O_ATTP + warp * 32 + mt * 16 + r4]     = plo[mt];
                smf[O_ATTP + warp * 32 + mt * 16 + 8 + r4] = phi[mt];
            }
        }
    }
    __syncthreads();
    if (tid < TE) {
        float s = 0.0f;
        #pragma unroll
        for (int w = 0; w < 8; w++) s += smf[O_ATTP + w * 32 + tid];
        smf[O_SATT + tid] = sigmoid_f(s + batt[0]);
    }
    __syncthreads();

    // apply attention: edge_out + agg red.v2 + sEf (tf32, for layer 3)
    #pragma unroll
    for (int mt = 0; mt < 2; mt++) {
        int elo = mt * 16 + r4, ehi = elo + 8;
        float attlo = smf[O_SATT + elo], atthi = smf[O_SATT + ehi];
        bool vlo = (e0 + elo) < EDGES, vhi = (e0 + ehi) < EDGES;
        long long glo = (long long)sRow[elo] * D;
        long long ghi = (long long)sRow[ehi] * D;
        float* out_lo = edge_out + (e0 + elo) * D;
        float* out_hi = edge_out + (e0 + ehi) * D;
        #pragma unroll
        for (int nt = 0; nt < 2; nt++) {
            int n0 = warp * 16 + nt * 8 + 2 * c;
            float f0 = acc[mt][nt][0] * attlo, f1 = acc[mt][nt][1] * attlo;
            float f2 = acc[mt][nt][2] * atthi, f3 = acc[mt][nt][3] * atthi;
            if (vlo) {
                *(float2*)(out_lo + n0) = make_float2(f0, f1);
                red2(g_agg + glo + n0, f0, f1);
            }
            if (vhi) {
                *(float2*)(out_hi + n0) = make_float2(f2, f3);
                red2(g_agg + ghi + n0, f2, f3);
            }
            *(uint2*)(smu + O_SEF + elo * RS2 + n0) = make_uint2(tfbits(f0), tfbits(f1));
            *(uint2*)(smu + O_SEF + ehi * RS2 + n0) = make_uint2(tfbits(f2), tfbits(f3));
            acc[mt][nt][0]=0; acc[mt][nt][1]=0; acc[mt][nt][2]=0; acc[mt][nt][3]=0;
        }
    }
    if (tid < TE) {
        *(float4*)(smf + O_SEF + tid * RS2 + 128) = make_float4(1.0f, 0, 0, 0);
        *(float4*)(smf + O_SEF + tid * RS2 + 132) = make_float4(0, 0, 0, 0);
    }
    __syncthreads();

    // ================= Layer 3 (coord MLP) =================
    run_layer_ns<NKS2>(aEF, RS2 * 4, g_wf3 + 32 * warp + lane, acc);
    {
        float qlo[2] = {0,0}, qhi[2] = {0,0};
        #pragma unroll
        for (int mt = 0; mt < 2; mt++) {
            #pragma unroll
            for (int nt = 0; nt < 2; nt++) {
                int n0 = warp * 16 + nt * 8 + 2 * c;
                float2 w2 = *(const float2*)(Wc2 + n0);
                qlo[mt] += silu_f(acc[mt][nt][0]) * w2.x + silu_f(acc[mt][nt][1]) * w2.y;
                qhi[mt] += silu_f(acc[mt][nt][2]) * w2.x + silu_f(acc[mt][nt][3]) * w2.y;
            }
        }
        #pragma unroll
        for (int mt = 0; mt < 2; mt++) {
            qlo[mt] += __shfl_xor_sync(0xffffffffu, qlo[mt], 1);
            qlo[mt] += __shfl_xor_sync(0xffffffffu, qlo[mt], 2);
            qhi[mt] += __shfl_xor_sync(0xffffffffu, qhi[mt], 1);
            qhi[mt] += __shfl_xor_sync(0xffffffffu, qhi[mt], 2);
        }
        if (c == 0) {
            #pragma unroll
            for (int mt = 0; mt < 2; mt++) {
                smf[O_CWP + warp * 32 + mt * 16 + r4]     = qlo[mt];
                smf[O_CWP + warp * 32 + mt * 16 + 8 + r4] = qhi[mt];
            }
        }
    }
    __syncthreads();
    if (tid < TE && (e0 + tid) < EDGES) {
        float cw = 0.0f;
        #pragma unroll
        for (int w = 0; w < 8; w++) cw += smf[O_CWP + w * 32 + tid];
        int n = sRow[tid];
        atomicAdd(g_ts + n * 3 + 0, clampt(smf[O_SCD + tid * 4 + 0] * cw));
        atomicAdd(g_ts + n * 3 + 1, clampt(smf[O_SCD + tid * 4 + 1] * cw));
        atomicAdd(g_ts + n * 3 + 2, clampt(smf[O_SCD + tid * 4 + 2] * cw));
        atomicAdd(g_cnt + n, 1.0f);
    }
}

// ---------------- node kernel ----------------
#define TN 32
#define O_XN    0
#define O_MIDN  (TN * RS1)                   // 8576
#define NSM_WORDS (O_MIDN + TN * RS2)        // 13056 words = 52224 B -> 4 CTA/SM

__global__ void __launch_bounds__(NTH) node_kernel(
    const float* __restrict__ h, const float* __restrict__ coord,
    float* __restrict__ h_out, float* __restrict__ coord_out)
{
    extern __shared__ uint32_t smu[];
    float* smf = (float*)smu;

    const int tid  = threadIdx.x;
    const int lane = tid & 31;
    const int warp = tid >> 5;
    const int c    = lane & 3;
    const int r4   = lane >> 2;
    const int n0b  = blockIdx.x * TN;
    const int ltile = lane >> 3, li = lane & 7;
    const int lrow  = (ltile & 1) * 8 + li;
    const int lcol  = (ltile >> 1) * 16;
    const uint32_t smb = (uint32_t)__cvta_generic_to_shared(smu);
    const uint32_t aXN   = smb + (O_XN   * 4) + lrow * (RS1 * 4) + lcol;
    const uint32_t aMIDN = smb + (O_MIDN * 4) + lrow * (RS2 * 4) + lcol;

    // gather [h | agg] -> sXN (tf32), warp w fills rows w*4..+4
    for (int i = 0; i < 4; i++) {
        int row = warp * 4 + i;
        int n = n0b + row;
        float4 tv = make_float4(0, 0, 0, 0), tw = make_float4(0, 0, 0, 0);
        if (n < NODES) {
            float4 v = *(const float4*)(h + (long long)n * D + lane * 4);
            float4 w = *(const float4*)(g_agg + (long long)n * D + lane * 4);
            tv = make_float4(tf32r(v.x), tf32r(v.y), tf32r(v.z), tf32r(v.w));
            tw = make_float4(tf32r(w.x), tf32r(w.y), tf32r(w.z), tf32r(w.w));
        }
        *(float4*)(smf + O_XN + row * RS1 + lane * 4) = tv;
        *(float4*)(smf + O_XN + row * RS1 + 128 + lane * 4) = tw;
    }
    if (tid < TN) {
        *(float4*)(smf + O_XN + tid * RS1 + 256) = make_float4(1.0f, 0, 0, 0);
        *(float4*)(smf + O_XN + tid * RS1 + 260) = make_float4(0, 0, 0, 0);
    }
    __syncthreads();

    float acc[2][2][4];
    #pragma unroll
    for (int m = 0; m < 2; m++)
        #pragma unroll
        for (int n = 0; n < 2; n++)
            { acc[m][n][0]=0; acc[m][n][1]=0; acc[m][n][2]=0; acc[m][n][3]=0; }

    run_layer_ns<NKS1>(aXN, RS1 * 4, g_wf4 + 32 * warp + lane, acc);

    #pragma unroll
    for (int mt = 0; mt < 2; mt++) {
        int rlo = mt * 16 + r4;
        #pragma unroll
        for (int nt = 0; nt < 2; nt++) {
            int n0 = warp * 16 + nt * 8 + 2 * c;
            *(uint2*)(smu + O_MIDN + rlo * RS2 + n0) =
                make_uint2(tfbits(silu_f(acc[mt][nt][0])), tfbits(silu_f(acc[mt][nt][1])));
            *(uint2*)(smu + O_MIDN + (rlo + 8) * RS2 + n0) =
                make_uint2(tfbits(silu_f(acc[mt][nt][2])), tfbits(silu_f(acc[mt][nt][3])));
            acc[mt][nt][0]=0; acc[mt][nt][1]=0; acc[mt][nt][2]=0; acc[mt][nt][3]=0;
        }
    }
    if (tid < TN) {
        *(float4*)(smf + O_MIDN + tid * RS2 + 128) = make_float4(1.0f, 0, 0, 0);
        *(float4*)(smf + O_MIDN + tid * RS2 + 132) = make_float4(0, 0, 0, 0);
    }
    __syncthreads();

    run_layer_ns<NKS2>(aMIDN, RS2 * 4, g_wf5 + 32 * warp + lane, acc);

    // h_out = h + acc
    #pragma unroll
    for (int mt = 0; mt < 2; mt++) {
        int nlo = n0b + mt * 16 + r4, nhi = nlo + 8;
        #pragma unroll
        for (int nt = 0; nt < 2; nt++) {
            int n0 = warp * 16 + nt * 8 + 2 * c;
            if (nlo < NODES) {
                float2 hv = *(const float2*)(h + (long long)nlo * D + n0);
                *(float2*)(h_out + (long long)nlo * D + n0) =
                    make_float2(hv.x + acc[mt][nt][0], hv.y + acc[mt][nt][1]);
            }
            if (nhi < NODES) {
                float2 hv = *(const float2*)(h + (long long)nhi * D + n0);
                *(float2*)(h_out + (long long)nhi * D + n0) =
                    make_float2(hv.x + acc[mt][nt][2], hv.y + acc[mt][nt][3]);
            }
        }
    }

    // coord_out = coord + clip(mean(trans))
    if (tid < TN) {
        int n = n0b + tid;
        if (n < NODES) {
            float cden = fmaxf(g_cnt[n], 1.0f);
            #pragma unroll
            for (int d3 = 0; d3 < 3; d3++) {
                float a = g_ts[n * 3 + d3] / cden;
                a = fminf(fmaxf(a, -MAXT), MAXT);
                coord_out[n * 3 + d3] = coord[n * 3 + d3] + a;
            }
        }
    }
}

// ---------------- launch ----------------
extern "C" void kernel_launch(void* const* d_in, const int* in_sizes, int n_in,
                              void* d_out, int out_size)
{
    const float* h     = (const float*)d_in[0];
    const int*   ei    = (const int*)d_in[1];
    const float* coord = (const float*)d_in[2];
    const float* We1   = (const float*)d_in[3];
    const float* be1   = (const float*)d_in[4];
    const float* We2   = (const float*)d_in[5];
    const float* be2   = (const float*)d_in[6];
    const float* Watt  = (const float*)d_in[7];
    const float* batt  = (const float*)d_in[8];
    const float* Wc1   = (const float*)d_in[9];
    const float* bc1   = (const float*)d_in[10];
    const float* Wc2   = (const float*)d_in[11];
    const float* Wn1   = (const float*)d_in[12];
    const float* bn1   = (const float*)d_in[13];
    const float* Wn2   = (const float*)d_in[14];
    const float* bn2   = (const float*)d_in[15];

    float* out       = (float*)d_out;
    float* h_out     = out;
    float* coord_out = out + (size_t)NODES * D;
    float* edge_out  = coord_out + (size_t)NODES * 3;

    size_t esm = (size_t)ESM_WORDS * sizeof(uint32_t);
    size_t nsm = (size_t)NSM_WORDS * sizeof(uint32_t);

    cudaFuncSetAttribute(edge_kernel, cudaFuncAttributeMaxDynamicSharedMemorySize, (int)esm);
    cudaFuncSetAttribute(node_kernel, cudaFuncAttributeMaxDynamicSharedMemorySize, (int)nsm);

    zero_kernel<<<512, 256>>>();
    int prep_threads = 2 * NKS1 * 8 * 32 + 3 * NKS2 * 8 * 32;
    prep_kernel<<<(prep_threads + 255) / 256, 256>>>(
        We1, be1, We2, be2, Wc1, bc1, Wn1, bn1, Wn2, bn2);
    edge_kernel<<<(EDGES + TE - 1) / TE, NTH, esm>>>(h, ei, coord, Watt, batt, Wc2, edge_out);
    node_kernel<<<(NODES + TN - 1) / TN, NTH, nsm>>>(h, coord, h_out, coord_out);
}